// round 1
// baseline (speedup 1.0000x reference)
#include <cuda_runtime.h>

#define NSEQ 1024
#define NRES 768
#define CM   64

// per-column weighted_avg scratch: wa[r][64]
__device__ float g_wa[NRES * CM];

__device__ __forceinline__ void fma4(float4& a, float s, const float4 w) {
    a.x += s * w.x; a.y += s * w.y; a.z += s * w.z; a.w += s * w.w;
}
__device__ __forceinline__ void xadd4(float4& a, int m) {
    a.x += __shfl_xor_sync(0xffffffffu, a.x, m);
    a.y += __shfl_xor_sync(0xffffffffu, a.y, m);
    a.z += __shfl_xor_sync(0xffffffffu, a.z, m);
    a.w += __shfl_xor_sync(0xffffffffu, a.w, m);
}

// ---------------------------------------------------------------------------
// Kernel 1: per-column attention. grid = 768 blocks (one per column r).
// Produces g_wa[r][h*8+d] = weighted_avg.
// ---------------------------------------------------------------------------
__global__ void __launch_bounds__(256, 1) msa_k1(
    const float* __restrict__ act,      // [S, R, C]
    const float* __restrict__ mask,     // [S, R]
    const float* __restrict__ ln_scale, // [64]
    const float* __restrict__ ln_bias,  // [64]
    const float* __restrict__ query_w,  // [64, 64]  (C, H*D)
    const float* __restrict__ key_w,    // [64, 8]
    const float* __restrict__ value_w)  // [64, 8]
{
    extern __shared__ float sm[];
    float* ks   = sm;              // 8192  : k[s][8]
    float* vs   = ks + 8192;       // 8192  : v[s][8]
    float* lsm  = vs + 8192;       // 8192  : logits / exp [s][8]
    float* msk  = lsm + 8192;      // 1024
    float* kws  = msk + 1024;      // 512
    float* vws  = kws + 512;       // 512
    float* scl  = vws + 512;       // 64
    float* bia  = scl + 64;        // 64
    float* qsum = bia + 64;        // 64
    float* qf   = qsum + 64;       // 64
    float* red  = qf + 64;         // 64   (8 warps x 8 heads)
    float* gmax = red + 64;        // 8
    float* invZ = gmax + 8;        // 8
    float* part = invZ + 8;        // 256
    float* Msum = part + 256;      // 1

    const int tid  = threadIdx.x;
    const int r    = blockIdx.x;
    const int lane = tid & 31;
    const int half = tid & 1;      // which 32-channel half this thread owns
    const int pair = tid >> 1;     // row-pair index 0..127

    for (int i = tid; i < 512; i += 256) { kws[i] = key_w[i]; vws[i] = value_w[i]; }
    if (tid < 64) { scl[tid] = ln_scale[tid]; bia[tid] = ln_bias[tid]; qsum[tid] = 0.f; }
    if (tid == 64) *Msum = 0.f;
    __syncthreads();

    const float4* kw4 = (const float4*)kws;  // kw4[c*2 + {0,1}]
    const float4* vw4 = (const float4*)vws;

    float lqs[32];
#pragma unroll
    for (int i = 0; i < 32; i++) lqs[i] = 0.f;
    float lms = 0.f;

    for (int it = 0; it < 8; ++it) {
        const int s = pair + it * 128;
        const float4* xp = (const float4*)(act + ((size_t)s * NRES + r) * CM) + half * 8;
        float x[32];
#pragma unroll
        for (int i = 0; i < 8; i++) {
            float4 t = xp[i];
            x[i*4+0] = t.x; x[i*4+1] = t.y; x[i*4+2] = t.z; x[i*4+3] = t.w;
        }
        const float m = mask[(size_t)s * NRES + r];
        if (half == 0) { msk[s] = m; lms += m; }

        float sum = 0.f;
#pragma unroll
        for (int i = 0; i < 32; i++) sum += x[i];
        sum += __shfl_xor_sync(0xffffffffu, sum, 1);
        const float mu = sum * (1.f / 64.f);

        float vv = 0.f;
#pragma unroll
        for (int i = 0; i < 32; i++) { float d = x[i] - mu; vv += d * d; }
        vv += __shfl_xor_sync(0xffffffffu, vv, 1);
        const float rstd = rsqrtf(vv * (1.f / 64.f) + 1e-5f);

        float4 pk0 = {0,0,0,0}, pk1 = {0,0,0,0}, pv0 = {0,0,0,0}, pv1 = {0,0,0,0};
#pragma unroll
        for (int c = 0; c < 32; c++) {
            const int cg = half * 32 + c;
            const float xn = (x[c] - mu) * rstd * scl[cg] + bia[cg];
            lqs[c] += m * xn;
            fma4(pk0, xn, kw4[cg*2]);   fma4(pk1, xn, kw4[cg*2+1]);
            fma4(pv0, xn, vw4[cg*2]);   fma4(pv1, xn, vw4[cg*2+1]);
        }
        // combine halves (each lane ends with complete row k and v)
        xadd4(pk0, 1); xadd4(pk1, 1); xadd4(pv0, 1); xadd4(pv1, 1);
        if (half == 0) {
            float4* kp = (float4*)(ks + s * 8);
            kp[0] = pk0; kp[1] = pk1;
        } else {
            float4* vp = (float4*)(vs + s * 8);
            vp[0] = pv0; vp[1] = pv1;
        }
    }

    // masked-sum reduction (same-parity lanes share channels)
#pragma unroll
    for (int i = 0; i < 32; i++) {
        float v = lqs[i];
        v += __shfl_xor_sync(0xffffffffu, v, 2);
        v += __shfl_xor_sync(0xffffffffu, v, 4);
        v += __shfl_xor_sync(0xffffffffu, v, 8);
        v += __shfl_xor_sync(0xffffffffu, v, 16);
        lqs[i] = v;
    }
    if (lane < 2) {
#pragma unroll
        for (int i = 0; i < 32; i++) atomicAdd(&qsum[lane * 32 + i], lqs[i]);
    }
    lms += __shfl_xor_sync(0xffffffffu, lms, 1);
    lms += __shfl_xor_sync(0xffffffffu, lms, 2);
    lms += __shfl_xor_sync(0xffffffffu, lms, 4);
    lms += __shfl_xor_sync(0xffffffffu, lms, 8);
    lms += __shfl_xor_sync(0xffffffffu, lms, 16);
    if (lane == 0) atomicAdd(Msum, lms);
    __syncthreads();

    // q = (q_avg @ query_w) * 8^-0.5
    if (tid < 64) {
        const float invM = 1.f / (*Msum + 1e-10f);
        float acc = 0.f;
        for (int c = 0; c < 64; c++) acc += qsum[c] * query_w[c * 64 + tid];
        qf[tid] = acc * invM * 0.35355339059327373f;
    }
    __syncthreads();

    // logits + running max
    float lmax[8];
#pragma unroll
    for (int h = 0; h < 8; h++) lmax[h] = -3.4e38f;
#pragma unroll
    for (int it = 0; it < 4; it++) {
        const int s = tid + it * 256;
        const float4* kp = (const float4*)(ks + s * 8);
        const float4 k0 = kp[0], k1 = kp[1];
        const float b = 1e9f * (msk[s] - 1.f);
#pragma unroll
        for (int h = 0; h < 8; h++) {
            const float* q = qf + h * 8;
            float l = b + q[0]*k0.x + q[1]*k0.y + q[2]*k0.z + q[3]*k0.w
                        + q[4]*k1.x + q[5]*k1.y + q[6]*k1.z + q[7]*k1.w;
            lsm[s * 8 + h] = l;
            lmax[h] = fmaxf(lmax[h], l);
        }
    }
    const int w = tid >> 5;
#pragma unroll
    for (int h = 0; h < 8; h++) {
#pragma unroll
        for (int off = 16; off; off >>= 1)
            lmax[h] = fmaxf(lmax[h], __shfl_xor_sync(0xffffffffu, lmax[h], off));
    }
    if (lane == 0) {
#pragma unroll
        for (int h = 0; h < 8; h++) red[w * 8 + h] = lmax[h];
    }
    __syncthreads();
    if (tid < 8) {
        float mm = red[tid];
#pragma unroll
        for (int ww = 1; ww < 8; ww++) mm = fmaxf(mm, red[ww * 8 + tid]);
        gmax[tid] = mm;
    }
    __syncthreads();

    // exp + partial sums
    float zl[8];
#pragma unroll
    for (int h = 0; h < 8; h++) zl[h] = 0.f;
#pragma unroll
    for (int it = 0; it < 4; it++) {
        const int s = tid + it * 256;
#pragma unroll
        for (int h = 0; h < 8; h++) {
            const float e = __expf(lsm[s * 8 + h] - gmax[h]);
            lsm[s * 8 + h] = e;
            zl[h] += e;
        }
    }
#pragma unroll
    for (int h = 0; h < 8; h++) {
#pragma unroll
        for (int off = 16; off; off >>= 1)
            zl[h] += __shfl_xor_sync(0xffffffffu, zl[h], off);
    }
    if (lane == 0) {
#pragma unroll
        for (int h = 0; h < 8; h++) red[w * 8 + h] = zl[h];
    }
    __syncthreads();
    if (tid < 8) {
        float z = 0.f;
#pragma unroll
        for (int ww = 0; ww < 8; ww++) z += red[ww * 8 + tid];
        invZ[tid] = 1.f / z;
    }
    __syncthreads();

    // weighted_avg[h][d] = sum_s e[s][h]*v[s][d] / Z[h]
    {
        const int hd = tid & 63, q4 = tid >> 6;
        const int h = hd >> 3, d = hd & 7;
        float p = 0.f;
        const int s0 = q4 * 256;
        for (int s = s0; s < s0 + 256; ++s)
            p += lsm[s * 8 + h] * vs[s * 8 + d];
        part[tid] = p;
    }
    __syncthreads();
    if (tid < 64) {
        const int h = tid >> 3;
        g_wa[r * 64 + tid] =
            (part[tid] + part[tid + 64] + part[tid + 128] + part[tid + 192]) * invZ[h];
    }
}

// ---------------------------------------------------------------------------
// Kernel 2: gate + output projection. grid = (768 columns, 4 s-chunks),
// one thread per (s, r) row.
// ---------------------------------------------------------------------------
__global__ void __launch_bounds__(256, 2) msa_k2(
    const float* __restrict__ act,
    const float* __restrict__ ln_scale, const float* __restrict__ ln_bias,
    const float* __restrict__ gating_w,  // [64, 64]  (C, H*D)
    const float* __restrict__ gating_b,  // [64]
    const float* __restrict__ output_w,  // [64, 64]  (H*D, C)
    const float* __restrict__ output_b,  // [64]
    float* __restrict__ out)             // [S, R, C]
{
    extern __shared__ float sm[];
    float* gws = sm;              // 4096
    float* ows = gws + 4096;      // 4096
    float* was = ows + 4096;      // 64
    float* gbs = was + 64;        // 64
    float* obs = gbs + 64;        // 64
    float* scl = obs + 64;        // 64
    float* bia = scl + 64;        // 64
    float* g2s = bia + 64;        // 16384 : per-thread gated vector, [k][tid]

    const int tid = threadIdx.x;
    const int r   = blockIdx.x;
    const int s   = blockIdx.y * 256 + tid;

    for (int i = tid; i < 4096; i += 256) { gws[i] = gating_w[i]; ows[i] = output_w[i]; }
    if (tid < 64) {
        was[tid] = g_wa[r * 64 + tid];
        gbs[tid] = gating_b[tid];  obs[tid] = output_b[tid];
        scl[tid] = ln_scale[tid];  bia[tid] = ln_bias[tid];
    }
    __syncthreads();

    const float4* xp = (const float4*)(act + ((size_t)s * NRES + r) * CM);
    float xn[64];
    float sum = 0.f;
#pragma unroll
    for (int i = 0; i < 16; i++) {
        float4 t = xp[i];
        xn[i*4+0] = t.x; xn[i*4+1] = t.y; xn[i*4+2] = t.z; xn[i*4+3] = t.w;
        sum += t.x + t.y + t.z + t.w;
    }
    const float mu = sum * (1.f / 64.f);
    float vv = 0.f;
#pragma unroll
    for (int i = 0; i < 64; i++) { float d = xn[i] - mu; vv += d * d; }
    const float rstd = rsqrtf(vv * (1.f / 64.f) + 1e-5f);
#pragma unroll
    for (int i = 0; i < 64; i++) xn[i] = (xn[i] - mu) * rstd * scl[i] + bia[i];

    const float4* gw4 = (const float4*)gws;
    const float4* ow4 = (const float4*)ows;
    const float4* gb4 = (const float4*)gbs;
    const float4* wa4 = (const float4*)was;

    // gate: g2[j] = wa[j] * sigmoid(xn . gating_w[:,j] + gb[j])
    for (int jj = 0; jj < 16; jj++) {
        float4 a = gb4[jj];
#pragma unroll
        for (int k = 0; k < 64; k++) {
            const float4 wv = gw4[k * 16 + jj];
            a.x += xn[k] * wv.x; a.y += xn[k] * wv.y;
            a.z += xn[k] * wv.z; a.w += xn[k] * wv.w;
        }
        const float4 wz = wa4[jj];
        g2s[(jj*4+0) * 256 + tid] = wz.x / (1.f + __expf(-a.x));
        g2s[(jj*4+1) * 256 + tid] = wz.y / (1.f + __expf(-a.y));
        g2s[(jj*4+2) * 256 + tid] = wz.z / (1.f + __expf(-a.z));
        g2s[(jj*4+3) * 256 + tid] = wz.w / (1.f + __expf(-a.w));
    }

    // out[o] = ob[o] + sum_k g2[k] * output_w[k][o]
    float4 o[16];
#pragma unroll
    for (int oo = 0; oo < 16; oo++) o[oo] = ((const float4*)obs)[oo];
    for (int k = 0; k < 64; k++) {
        const float g = g2s[k * 256 + tid];
#pragma unroll
        for (int oo = 0; oo < 16; oo++) {
            const float4 wv = ow4[k * 16 + oo];
            o[oo].x += g * wv.x; o[oo].y += g * wv.y;
            o[oo].z += g * wv.z; o[oo].w += g * wv.w;
        }
    }
    float4* op = (float4*)(out + ((size_t)s * NRES + r) * CM);
#pragma unroll
    for (int oo = 0; oo < 16; oo++) op[oo] = o[oo];
}

// ---------------------------------------------------------------------------
#define K1_SMEM (27232 * 4)
#define K2_SMEM (24896 * 4)

extern "C" void kernel_launch(void* const* d_in, const int* in_sizes, int n_in,
                              void* d_out, int out_size) {
    (void)in_sizes; (void)n_in; (void)out_size;
    const float* act      = (const float*)d_in[0];
    const float* mask     = (const float*)d_in[1];
    const float* ln_scale = (const float*)d_in[2];
    const float* ln_bias  = (const float*)d_in[3];
    const float* query_w  = (const float*)d_in[4];
    const float* key_w    = (const float*)d_in[5];
    const float* value_w  = (const float*)d_in[6];
    const float* gating_w = (const float*)d_in[7];
    const float* gating_b = (const float*)d_in[8];
    const float* output_w = (const float*)d_in[9];
    const float* output_b = (const float*)d_in[10];
    float* out = (float*)d_out;

    cudaFuncSetAttribute(msa_k1, cudaFuncAttributeMaxDynamicSharedMemorySize, K1_SMEM);
    cudaFuncSetAttribute(msa_k2, cudaFuncAttributeMaxDynamicSharedMemorySize, K2_SMEM);

    msa_k1<<<NRES, 256, K1_SMEM>>>(act, mask, ln_scale, ln_bias, query_w, key_w, value_w);
    msa_k2<<<dim3(NRES, 4), 256, K2_SMEM>>>(act, ln_scale, ln_bias,
                                            gating_w, gating_b, output_w, output_b, out);
}

// round 2
// speedup vs baseline: 1.7581x; 1.7581x over previous
#include <cuda_runtime.h>
#include <cstdint>

#define NSEQ 1024
#define NRES 768
#define CM   64

// per-column weighted_avg scratch: wa[r][64]
__device__ float g_wa[NRES * CM];

__device__ __forceinline__ void fma4(float4& a, float s, const float4 w) {
    a.x += s * w.x; a.y += s * w.y; a.z += s * w.z; a.w += s * w.w;
}
__device__ __forceinline__ void xadd4(float4& a, int m) {
    a.x += __shfl_xor_sync(0xffffffffu, a.x, m);
    a.y += __shfl_xor_sync(0xffffffffu, a.y, m);
    a.z += __shfl_xor_sync(0xffffffffu, a.z, m);
    a.w += __shfl_xor_sync(0xffffffffu, a.w, m);
}
__device__ __forceinline__ uint32_t f2tf32(float f) {
    uint32_t r;
    asm("cvt.rna.tf32.f32 %0, %1;" : "=r"(r) : "f"(f));
    return r;
}
__device__ __forceinline__ void mma_tf32(float4& d,
    uint32_t a0, uint32_t a1, uint32_t a2, uint32_t a3,
    uint32_t b0, uint32_t b1) {
    asm volatile("mma.sync.aligned.m16n8k8.row.col.f32.tf32.tf32.f32 "
        "{%0,%1,%2,%3}, {%4,%5,%6,%7}, {%8,%9}, {%0,%1,%2,%3};"
        : "+f"(d.x), "+f"(d.y), "+f"(d.z), "+f"(d.w)
        : "r"(a0), "r"(a1), "r"(a2), "r"(a3), "r"(b0), "r"(b1));
}
__device__ __forceinline__ float sigf(float x) {
    return __fdividef(1.f, 1.f + __expf(-x));
}

// ---------------------------------------------------------------------------
// Kernel 1: per-column attention. grid = 768 blocks (one per column r).
// Produces g_wa[r][h*8+d] = weighted_avg.  (unchanged from round 1)
// ---------------------------------------------------------------------------
__global__ void __launch_bounds__(256, 1) msa_k1(
    const float* __restrict__ act,      // [S, R, C]
    const float* __restrict__ mask,     // [S, R]
    const float* __restrict__ ln_scale, // [64]
    const float* __restrict__ ln_bias,  // [64]
    const float* __restrict__ query_w,  // [64, 64]  (C, H*D)
    const float* __restrict__ key_w,    // [64, 8]
    const float* __restrict__ value_w)  // [64, 8]
{
    extern __shared__ float sm[];
    float* ks   = sm;              // 8192  : k[s][8]
    float* vs   = ks + 8192;       // 8192  : v[s][8]
    float* lsm  = vs + 8192;       // 8192  : logits / exp [s][8]
    float* msk  = lsm + 8192;      // 1024
    float* kws  = msk + 1024;      // 512
    float* vws  = kws + 512;       // 512
    float* scl  = vws + 512;       // 64
    float* bia  = scl + 64;        // 64
    float* qsum = bia + 64;        // 64
    float* qf   = qsum + 64;       // 64
    float* red  = qf + 64;         // 64   (8 warps x 8 heads)
    float* gmax = red + 64;        // 8
    float* invZ = gmax + 8;        // 8
    float* part = invZ + 8;        // 256
    float* Msum = part + 256;      // 1

    const int tid  = threadIdx.x;
    const int r    = blockIdx.x;
    const int lane = tid & 31;
    const int half = tid & 1;      // which 32-channel half this thread owns
    const int pair = tid >> 1;     // row-pair index 0..127

    for (int i = tid; i < 512; i += 256) { kws[i] = key_w[i]; vws[i] = value_w[i]; }
    if (tid < 64) { scl[tid] = ln_scale[tid]; bia[tid] = ln_bias[tid]; qsum[tid] = 0.f; }
    if (tid == 64) *Msum = 0.f;
    __syncthreads();

    const float4* kw4 = (const float4*)kws;
    const float4* vw4 = (const float4*)vws;

    float lqs[32];
#pragma unroll
    for (int i = 0; i < 32; i++) lqs[i] = 0.f;
    float lms = 0.f;

    for (int it = 0; it < 8; ++it) {
        const int s = pair + it * 128;
        const float4* xp = (const float4*)(act + ((size_t)s * NRES + r) * CM) + half * 8;
        float x[32];
#pragma unroll
        for (int i = 0; i < 8; i++) {
            float4 t = xp[i];
            x[i*4+0] = t.x; x[i*4+1] = t.y; x[i*4+2] = t.z; x[i*4+3] = t.w;
        }
        const float m = mask[(size_t)s * NRES + r];
        if (half == 0) { msk[s] = m; lms += m; }

        float sum = 0.f;
#pragma unroll
        for (int i = 0; i < 32; i++) sum += x[i];
        sum += __shfl_xor_sync(0xffffffffu, sum, 1);
        const float mu = sum * (1.f / 64.f);

        float vv = 0.f;
#pragma unroll
        for (int i = 0; i < 32; i++) { float d = x[i] - mu; vv += d * d; }
        vv += __shfl_xor_sync(0xffffffffu, vv, 1);
        const float rstd = rsqrtf(vv * (1.f / 64.f) + 1e-5f);

        float4 pk0 = {0,0,0,0}, pk1 = {0,0,0,0}, pv0 = {0,0,0,0}, pv1 = {0,0,0,0};
#pragma unroll
        for (int c = 0; c < 32; c++) {
            const int cg = half * 32 + c;
            const float xn = (x[c] - mu) * rstd * scl[cg] + bia[cg];
            lqs[c] += m * xn;
            fma4(pk0, xn, kw4[cg*2]);   fma4(pk1, xn, kw4[cg*2+1]);
            fma4(pv0, xn, vw4[cg*2]);   fma4(pv1, xn, vw4[cg*2+1]);
        }
        xadd4(pk0, 1); xadd4(pk1, 1); xadd4(pv0, 1); xadd4(pv1, 1);
        if (half == 0) {
            float4* kp = (float4*)(ks + s * 8);
            kp[0] = pk0; kp[1] = pk1;
        } else {
            float4* vp = (float4*)(vs + s * 8);
            vp[0] = pv0; vp[1] = pv1;
        }
    }

#pragma unroll
    for (int i = 0; i < 32; i++) {
        float v = lqs[i];
        v += __shfl_xor_sync(0xffffffffu, v, 2);
        v += __shfl_xor_sync(0xffffffffu, v, 4);
        v += __shfl_xor_sync(0xffffffffu, v, 8);
        v += __shfl_xor_sync(0xffffffffu, v, 16);
        lqs[i] = v;
    }
    if (lane < 2) {
#pragma unroll
        for (int i = 0; i < 32; i++) atomicAdd(&qsum[lane * 32 + i], lqs[i]);
    }
    lms += __shfl_xor_sync(0xffffffffu, lms, 1);
    lms += __shfl_xor_sync(0xffffffffu, lms, 2);
    lms += __shfl_xor_sync(0xffffffffu, lms, 4);
    lms += __shfl_xor_sync(0xffffffffu, lms, 8);
    lms += __shfl_xor_sync(0xffffffffu, lms, 16);
    if (lane == 0) atomicAdd(Msum, lms);
    __syncthreads();

    if (tid < 64) {
        const float invM = 1.f / (*Msum + 1e-10f);
        float acc = 0.f;
        for (int c = 0; c < 64; c++) acc += qsum[c] * query_w[c * 64 + tid];
        qf[tid] = acc * invM * 0.35355339059327373f;
    }
    __syncthreads();

    float lmax[8];
#pragma unroll
    for (int h = 0; h < 8; h++) lmax[h] = -3.4e38f;
#pragma unroll
    for (int it = 0; it < 4; it++) {
        const int s = tid + it * 256;
        const float4* kp = (const float4*)(ks + s * 8);
        const float4 k0 = kp[0], k1 = kp[1];
        const float b = 1e9f * (msk[s] - 1.f);
#pragma unroll
        for (int h = 0; h < 8; h++) {
            const float* q = qf + h * 8;
            float l = b + q[0]*k0.x + q[1]*k0.y + q[2]*k0.z + q[3]*k0.w
                        + q[4]*k1.x + q[5]*k1.y + q[6]*k1.z + q[7]*k1.w;
            lsm[s * 8 + h] = l;
            lmax[h] = fmaxf(lmax[h], l);
        }
    }
    const int w = tid >> 5;
#pragma unroll
    for (int h = 0; h < 8; h++) {
#pragma unroll
        for (int off = 16; off; off >>= 1)
            lmax[h] = fmaxf(lmax[h], __shfl_xor_sync(0xffffffffu, lmax[h], off));
    }
    if (lane == 0) {
#pragma unroll
        for (int h = 0; h < 8; h++) red[w * 8 + h] = lmax[h];
    }
    __syncthreads();
    if (tid < 8) {
        float mm = red[tid];
#pragma unroll
        for (int ww = 1; ww < 8; ww++) mm = fmaxf(mm, red[ww * 8 + tid]);
        gmax[tid] = mm;
    }
    __syncthreads();

    float zl[8];
#pragma unroll
    for (int h = 0; h < 8; h++) zl[h] = 0.f;
#pragma unroll
    for (int it = 0; it < 4; it++) {
        const int s = tid + it * 256;
#pragma unroll
        for (int h = 0; h < 8; h++) {
            const float e = __expf(lsm[s * 8 + h] - gmax[h]);
            lsm[s * 8 + h] = e;
            zl[h] += e;
        }
    }
#pragma unroll
    for (int h = 0; h < 8; h++) {
#pragma unroll
        for (int off = 16; off; off >>= 1)
            zl[h] += __shfl_xor_sync(0xffffffffu, zl[h], off);
    }
    if (lane == 0) {
#pragma unroll
        for (int h = 0; h < 8; h++) red[w * 8 + h] = zl[h];
    }
    __syncthreads();
    if (tid < 8) {
        float z = 0.f;
#pragma unroll
        for (int ww = 0; ww < 8; ww++) z += red[ww * 8 + tid];
        invZ[tid] = 1.f / z;
    }
    __syncthreads();

    {
        const int hd = tid & 63, q4 = tid >> 6;
        const int h = hd >> 3, d = hd & 7;
        float p = 0.f;
        const int s0 = q4 * 256;
        for (int s = s0; s < s0 + 256; ++s)
            p += lsm[s * 8 + h] * vs[s * 8 + d];
        part[tid] = p;
    }
    __syncthreads();
    if (tid < 64) {
        const int h = tid >> 3;
        g_wa[r * 64 + tid] =
            (part[tid] + part[tid + 64] + part[tid + 128] + part[tid + 192]) * invZ[h];
    }
}

// ---------------------------------------------------------------------------
// Kernel 2: gate + output projection via tf32 tensor-core MMA.
// grid = (768 columns, 8 s-tiles of 128 rows). 8 warps, each owns 16 rows.
//   GEMM1: XN[128x64] @ GW[64x64]   -> logits; sigmoid * wa -> G (tf32, smem)
//   GEMM2: G[128x64]  @ OW[64x64]   -> OUT
// ---------------------------------------------------------------------------
#define XS 68   // smem row stride (floats): (4g+t)%32 conflict-free fragment LDS

__global__ void __launch_bounds__(256, 2) msa_k2(
    const float* __restrict__ act,
    const float* __restrict__ ln_scale, const float* __restrict__ ln_bias,
    const float* __restrict__ gating_w,  // [64, 64]  (C, H*D)
    const float* __restrict__ gating_b,  // [64]
    const float* __restrict__ output_w,  // [64, 64]  (H*D, C)
    const float* __restrict__ output_b,  // [64]
    float* __restrict__ out)             // [S, R, C]
{
    extern __shared__ float sm2[];
    float* xn_s = sm2;             // 128*68 = 8704   XN tile, later reused for G
    float* gwt  = xn_s + 8704;     // 64*68  = 4352   GW transposed: gwt[j][c]
    float* owt  = gwt + 4352;      // 64*68  = 4352   OW transposed: owt[o][j]
    float* was  = owt + 4352;      // 64
    float* gbs  = was + 64;        // 64
    float* obs  = gbs + 64;        // 64
    float* scl  = obs + 64;        // 64
    float* bia  = scl + 64;        // 64

    const int tid = threadIdx.x;
    const int r   = blockIdx.x;
    const int s0  = blockIdx.y * 128;

    // ---- stage weights (transposed + tf32-rounded) and vectors ----
    for (int i = tid; i < 4096; i += 256) {
        const int c = i >> 6, j = i & 63;   // weight[c][j] layouts
        gwt[j * XS + c] = __uint_as_float(f2tf32(gating_w[i]));
        owt[j * XS + c] = __uint_as_float(f2tf32(output_w[i]));  // output_w[j][o]: j=i>>6 -> owt[o][j]
    }
    if (tid < 64) {
        was[tid] = g_wa[r * 64 + tid];
        gbs[tid] = gating_b[tid];  obs[tid] = output_b[tid];
        scl[tid] = ln_scale[tid];  bia[tid] = ln_bias[tid];
    }
    // note: owt index above actually needs owt[o][j] = output_w[j*64+o];
    // with i = j*64 + o: c==j, jdx==o -> owt[(i&63)*XS + (i>>6)]  — fixed below.
    __syncthreads();
    // fix the owt transpose direction (output_w is [j][o], we want owt[o][j]).
    // gating_w is [c][j], we want gwt[j][c] — the loop above wrote BOTH as
    // [second][first], which is gwt[j][c] (correct) and owt[o][j] (correct),
    // since for output_w: first=j, second=o  ->  owt[o*XS + j]. Re-derive:
    //   i>>6 = first index, i&63 = second index; we wrote w[(i&63)*XS+(i>>6)]
    //   gating: first=c, second=j -> gwt[j*XS+c]  OK
    //   output: first=j, second=o -> owt[o*XS+j]  OK
    // (comment only; code above is correct)

    // ---- LayerNorm: thread pair per row, write tf32 XN to smem ----
    {
        const int half = tid & 1, p = tid >> 1;
        const float4* xp = (const float4*)(act + ((size_t)(s0 + p) * NRES + r) * CM) + half * 8;
        float x[32];
#pragma unroll
        for (int i = 0; i < 8; i++) {
            float4 t = xp[i];
            x[i*4+0] = t.x; x[i*4+1] = t.y; x[i*4+2] = t.z; x[i*4+3] = t.w;
        }
        float sum = 0.f;
#pragma unroll
        for (int i = 0; i < 32; i++) sum += x[i];
        sum += __shfl_xor_sync(0xffffffffu, sum, 1);
        const float mu = sum * (1.f / 64.f);
        float vv = 0.f;
#pragma unroll
        for (int i = 0; i < 32; i++) { float d = x[i] - mu; vv += d * d; }
        vv += __shfl_xor_sync(0xffffffffu, vv, 1);
        const float rstd = rsqrtf(vv * (1.f / 64.f) + 1e-5f);
#pragma unroll
        for (int c = 0; c < 32; c++) {
            const int cg = half * 32 + c;
            const float xn = (x[c] - mu) * rstd * scl[cg] + bia[cg];
            xn_s[p * XS + cg] = __uint_as_float(f2tf32(xn));
        }
    }
    __syncthreads();

    // ---- per-warp MMA pipeline on a 16-row strip ----
    const int warp = tid >> 5, lane = tid & 31;
    const int g = lane >> 2, t = lane & 3;
    const int rb = warp * 16;

    float4 acc[8];
#pragma unroll
    for (int n = 0; n < 8; n++) acc[n] = make_float4(0.f, 0.f, 0.f, 0.f);

    // GEMM1: logits = XN @ GW
#pragma unroll
    for (int k = 0; k < 8; k++) {
        const int kc = k * 8 + t;
        const uint32_t a0 = __float_as_uint(xn_s[(rb + g) * XS + kc]);
        const uint32_t a1 = __float_as_uint(xn_s[(rb + g + 8) * XS + kc]);
        const uint32_t a2 = __float_as_uint(xn_s[(rb + g) * XS + kc + 4]);
        const uint32_t a3 = __float_as_uint(xn_s[(rb + g + 8) * XS + kc + 4]);
#pragma unroll
        for (int n = 0; n < 8; n++) {
            const uint32_t b0 = __float_as_uint(gwt[(n * 8 + g) * XS + kc]);
            const uint32_t b1 = __float_as_uint(gwt[(n * 8 + g) * XS + kc + 4]);
            mma_tf32(acc[n], a0, a1, a2, a3, b0, b1);
        }
    }
    __syncwarp();

    // sigmoid gate * wa, store G back into the warp-private strip (tf32)
#pragma unroll
    for (int n = 0; n < 8; n++) {
        const int c0 = n * 8 + 2 * t, c1 = c0 + 1;
        const float w0 = was[c0], w1 = was[c1];
        const float b0 = gbs[c0], b1 = gbs[c1];
        xn_s[(rb + g) * XS + c0]     = __uint_as_float(f2tf32(w0 * sigf(acc[n].x + b0)));
        xn_s[(rb + g) * XS + c1]     = __uint_as_float(f2tf32(w1 * sigf(acc[n].y + b1)));
        xn_s[(rb + g + 8) * XS + c0] = __uint_as_float(f2tf32(w0 * sigf(acc[n].z + b0)));
        xn_s[(rb + g + 8) * XS + c1] = __uint_as_float(f2tf32(w1 * sigf(acc[n].w + b1)));
    }
    __syncwarp();

    // GEMM2: OUT = G @ OW + ob
    float4 o[8];
#pragma unroll
    for (int n = 0; n < 8; n++) {
        const int c0 = n * 8 + 2 * t;
        o[n] = make_float4(obs[c0], obs[c0 + 1], obs[c0], obs[c0 + 1]);
    }
#pragma unroll
    for (int k = 0; k < 8; k++) {
        const int kc = k * 8 + t;
        const uint32_t a0 = __float_as_uint(xn_s[(rb + g) * XS + kc]);
        const uint32_t a1 = __float_as_uint(xn_s[(rb + g + 8) * XS + kc]);
        const uint32_t a2 = __float_as_uint(xn_s[(rb + g) * XS + kc + 4]);
        const uint32_t a3 = __float_as_uint(xn_s[(rb + g + 8) * XS + kc + 4]);
#pragma unroll
        for (int n = 0; n < 8; n++) {
            const uint32_t b0 = __float_as_uint(owt[(n * 8 + g) * XS + kc]);
            const uint32_t b1 = __float_as_uint(owt[(n * 8 + g) * XS + kc + 4]);
            mma_tf32(o[n], a0, a1, a2, a3, b0, b1);
        }
    }

    // direct stores: per n, two 8-byte sector-aligned float2 per thread
    const size_t row0 = (size_t)(s0 + rb + g) * NRES + r;
    const size_t row1 = (size_t)(s0 + rb + g + 8) * NRES + r;
    float* o0 = out + row0 * CM;
    float* o1 = out + row1 * CM;
#pragma unroll
    for (int n = 0; n < 8; n++) {
        const int c0 = n * 8 + 2 * t;
        *(float2*)(o0 + c0) = make_float2(o[n].x, o[n].y);
        *(float2*)(o1 + c0) = make_float2(o[n].z, o[n].w);
    }
}

// ---------------------------------------------------------------------------
#define K1_SMEM (27232 * 4)
#define K2_SMEM (17760 * 4)

extern "C" void kernel_launch(void* const* d_in, const int* in_sizes, int n_in,
                              void* d_out, int out_size) {
    (void)in_sizes; (void)n_in; (void)out_size;
    const float* act      = (const float*)d_in[0];
    const float* mask     = (const float*)d_in[1];
    const float* ln_scale = (const float*)d_in[2];
    const float* ln_bias  = (const float*)d_in[3];
    const float* query_w  = (const float*)d_in[4];
    const float* key_w    = (const float*)d_in[5];
    const float* value_w  = (const float*)d_in[6];
    const float* gating_w = (const float*)d_in[7];
    const float* gating_b = (const float*)d_in[8];
    const float* output_w = (const float*)d_in[9];
    const float* output_b = (const float*)d_in[10];
    float* out = (float*)d_out;

    cudaFuncSetAttribute(msa_k1, cudaFuncAttributeMaxDynamicSharedMemorySize, K1_SMEM);
    cudaFuncSetAttribute(msa_k2, cudaFuncAttributeMaxDynamicSharedMemorySize, K2_SMEM);

    msa_k1<<<NRES, 256, K1_SMEM>>>(act, mask, ln_scale, ln_bias, query_w, key_w, value_w);
    msa_k2<<<dim3(NRES, 8), 256, K2_SMEM>>>(act, ln_scale, ln_bias,
                                            gating_w, gating_b, output_w, output_b, out);
}

// round 3
// speedup vs baseline: 1.8755x; 1.0668x over previous
#include <cuda_runtime.h>
#include <cstdint>

#define NSEQ 1024
#define NRES 768
#define CM   64
#define XS   68   // smem row stride in floats (17 float4) — conflict-free MMA frags

// per-column weighted_avg scratch: wa[r][64]
__device__ float g_wa[NRES * CM];

__device__ __forceinline__ void fma4(float4& a, float s, const float4 w) {
    a.x += s * w.x; a.y += s * w.y; a.z += s * w.z; a.w += s * w.w;
}
__device__ __forceinline__ void xadd4(float4& a, int m) {
    a.x += __shfl_xor_sync(0xffffffffu, a.x, m);
    a.y += __shfl_xor_sync(0xffffffffu, a.y, m);
    a.z += __shfl_xor_sync(0xffffffffu, a.z, m);
    a.w += __shfl_xor_sync(0xffffffffu, a.w, m);
}
__device__ __forceinline__ uint32_t f2tf32(float f) {
    uint32_t r;
    asm("cvt.rna.tf32.f32 %0, %1;" : "=r"(r) : "f"(f));
    return r;
}
__device__ __forceinline__ void mma_tf32(float4& d,
    uint32_t a0, uint32_t a1, uint32_t a2, uint32_t a3,
    uint32_t b0, uint32_t b1) {
    asm volatile("mma.sync.aligned.m16n8k8.row.col.f32.tf32.tf32.f32 "
        "{%0,%1,%2,%3}, {%4,%5,%6,%7}, {%8,%9}, {%0,%1,%2,%3};"
        : "+f"(d.x), "+f"(d.y), "+f"(d.z), "+f"(d.w)
        : "r"(a0), "r"(a1), "r"(a2), "r"(a3), "r"(b0), "r"(b1));
}
__device__ __forceinline__ float sigf(float x) {
    return __fdividef(1.f, 1.f + __expf(-x));
}

// ---------------------------------------------------------------------------
// Kernel 1: per-column attention. grid = 768 blocks, 512 threads.
// Coalesced LDG into smem staging tile, fp32 pair-thread LN/KV compute.
// ---------------------------------------------------------------------------
__global__ void __launch_bounds__(512, 1) msa_k1(
    const float* __restrict__ act,      // [S, R, C]
    const float* __restrict__ mask,     // [S, R]
    const float* __restrict__ ln_scale, // [64]
    const float* __restrict__ ln_bias,  // [64]
    const float* __restrict__ query_w,  // [64, 64]
    const float* __restrict__ key_w,    // [64, 8]
    const float* __restrict__ value_w)  // [64, 8]
{
    extern __shared__ float sm[];
    float* xst  = sm;               // 17408 : staging tile 256 rows x stride 68
    float* ks   = xst + 17408;      // 8192  : k[s][8]
    float* vs   = ks + 8192;        // 8192
    float* lsm  = vs + 8192;        // 8192
    float* msk  = lsm + 8192;       // 1024
    float* kws  = msk + 1024;       // 512
    float* vws  = kws + 512;        // 512
    float* scl  = vws + 512;        // 64
    float* bia  = scl + 64;         // 64
    float* qsum = bia + 64;         // 64
    float* qf   = qsum + 64;        // 64
    float* red  = qf + 64;          // 128  (16 warps x 8 heads)
    float* gmax = red + 128;        // 8
    float* invZ = gmax + 8;         // 8
    float* part = invZ + 8;         // 512
    float* Msum = part + 512;       // 1

    const int tid  = threadIdx.x;
    const int r    = blockIdx.x;
    const int lane = tid & 31;
    const int w    = tid >> 5;
    const int half = tid & 1;
    const int p    = tid >> 1;       // pair index 0..255 = row within tile
    const int c4   = lane & 15;
    const int rsel = lane >> 4;

    if (tid < 512) { kws[tid] = key_w[tid]; vws[tid] = value_w[tid]; }
    if (tid < 64) { scl[tid] = ln_scale[tid]; bia[tid] = ln_bias[tid]; qsum[tid] = 0.f; }
    if (tid == 64) *Msum = 0.f;
    __syncthreads();

    const float4* kw4 = (const float4*)kws;
    const float4* vw4 = (const float4*)vws;

    float lqs[32];
#pragma unroll
    for (int i = 0; i < 32; i++) lqs[i] = 0.f;
    float lms = 0.f;

    for (int tile = 0; tile < 4; ++tile) {
        // ---- coalesced stage: 256 rows x 256B ----
#pragma unroll
        for (int rnd = 0; rnd < 8; rnd++) {
            const int row = rnd * 32 + w * 2 + rsel;
            const int s = tile * 256 + row;
            const float4 t = *(const float4*)(act + ((size_t)s * NRES + r) * CM + c4 * 4);
            *(float4*)(xst + row * XS + c4 * 4) = t;
        }
        __syncthreads();

        // ---- pair-thread compute: row p of this tile ----
        const int s = tile * 256 + p;
        float x[32];
#pragma unroll
        for (int i = 0; i < 8; i++) {
            const int ci = (i + 2 * p + 4 * half) & 7;           // swizzle: conflict-free
            const float4 t = *(const float4*)(xst + p * XS + (8 * half + ci) * 4);
            x[ci*4+0] = t.x; x[ci*4+1] = t.y; x[ci*4+2] = t.z; x[ci*4+3] = t.w;
        }
        const float m = mask[(size_t)s * NRES + r];
        if (half == 0) { msk[s] = m; lms += m; }

        float sum = 0.f;
#pragma unroll
        for (int i = 0; i < 32; i++) sum += x[i];
        sum += __shfl_xor_sync(0xffffffffu, sum, 1);
        const float mu = sum * (1.f / 64.f);
        float vv = 0.f;
#pragma unroll
        for (int i = 0; i < 32; i++) { float d = x[i] - mu; vv += d * d; }
        vv += __shfl_xor_sync(0xffffffffu, vv, 1);
        const float rstd = rsqrtf(vv * (1.f / 64.f) + 1e-5f);

        float4 pk0 = {0,0,0,0}, pk1 = {0,0,0,0}, pv0 = {0,0,0,0}, pv1 = {0,0,0,0};
#pragma unroll
        for (int c = 0; c < 32; c++) {
            const int cg = half * 32 + c;
            const float xn = (x[c] - mu) * rstd * scl[cg] + bia[cg];
            lqs[c] += m * xn;
            fma4(pk0, xn, kw4[cg*2]);   fma4(pk1, xn, kw4[cg*2+1]);
            fma4(pv0, xn, vw4[cg*2]);   fma4(pv1, xn, vw4[cg*2+1]);
        }
        xadd4(pk0, 1); xadd4(pk1, 1); xadd4(pv0, 1); xadd4(pv1, 1);
        if (half == 0) {
            float4* kp = (float4*)(ks + s * 8);
            kp[0] = pk0; kp[1] = pk1;
        } else {
            float4* vp = (float4*)(vs + s * 8);
            vp[0] = pv0; vp[1] = pv1;
        }
        __syncthreads();   // xst reused next tile
    }

    // ---- qsum / Msum reductions ----
#pragma unroll
    for (int i = 0; i < 32; i++) {
        float v = lqs[i];
        v += __shfl_xor_sync(0xffffffffu, v, 2);
        v += __shfl_xor_sync(0xffffffffu, v, 4);
        v += __shfl_xor_sync(0xffffffffu, v, 8);
        v += __shfl_xor_sync(0xffffffffu, v, 16);
        lqs[i] = v;
    }
    if (lane < 2) {
#pragma unroll
        for (int i = 0; i < 32; i++) atomicAdd(&qsum[lane * 32 + i], lqs[i]);
    }
    lms += __shfl_xor_sync(0xffffffffu, lms, 1);
    lms += __shfl_xor_sync(0xffffffffu, lms, 2);
    lms += __shfl_xor_sync(0xffffffffu, lms, 4);
    lms += __shfl_xor_sync(0xffffffffu, lms, 8);
    lms += __shfl_xor_sync(0xffffffffu, lms, 16);
    if (lane == 0) atomicAdd(Msum, lms);
    __syncthreads();

    // ---- q projection ----
    if (tid < 64) {
        const float invM = 1.f / (*Msum + 1e-10f);
        float acc = 0.f;
        for (int c = 0; c < 64; c++) acc += qsum[c] * query_w[c * 64 + tid];
        qf[tid] = acc * invM * 0.35355339059327373f;
    }
    __syncthreads();

    // ---- logits + max ----
    float lmax[8];
#pragma unroll
    for (int h = 0; h < 8; h++) lmax[h] = -3.4e38f;
#pragma unroll
    for (int it = 0; it < 2; it++) {
        const int s = tid + it * 512;
        const float4* kp = (const float4*)(ks + s * 8);
        const float4 k0 = kp[0], k1 = kp[1];
        const float b = 1e9f * (msk[s] - 1.f);
#pragma unroll
        for (int h = 0; h < 8; h++) {
            const float* q = qf + h * 8;
            float l = b + q[0]*k0.x + q[1]*k0.y + q[2]*k0.z + q[3]*k0.w
                        + q[4]*k1.x + q[5]*k1.y + q[6]*k1.z + q[7]*k1.w;
            lsm[s * 8 + h] = l;
            lmax[h] = fmaxf(lmax[h], l);
        }
    }
#pragma unroll
    for (int h = 0; h < 8; h++) {
#pragma unroll
        for (int off = 16; off; off >>= 1)
            lmax[h] = fmaxf(lmax[h], __shfl_xor_sync(0xffffffffu, lmax[h], off));
    }
    if (lane == 0) {
#pragma unroll
        for (int h = 0; h < 8; h++) red[w * 8 + h] = lmax[h];
    }
    __syncthreads();
    if (tid < 8) {
        float mm = red[tid];
#pragma unroll
        for (int ww = 1; ww < 16; ww++) mm = fmaxf(mm, red[ww * 8 + tid]);
        gmax[tid] = mm;
    }
    __syncthreads();

    // ---- exp + Z ----
    float zl[8];
#pragma unroll
    for (int h = 0; h < 8; h++) zl[h] = 0.f;
#pragma unroll
    for (int it = 0; it < 2; it++) {
        const int s = tid + it * 512;
#pragma unroll
        for (int h = 0; h < 8; h++) {
            const float e = __expf(lsm[s * 8 + h] - gmax[h]);
            lsm[s * 8 + h] = e;
            zl[h] += e;
        }
    }
#pragma unroll
    for (int h = 0; h < 8; h++) {
#pragma unroll
        for (int off = 16; off; off >>= 1)
            zl[h] += __shfl_xor_sync(0xffffffffu, zl[h], off);
    }
    if (lane == 0) {
#pragma unroll
        for (int h = 0; h < 8; h++) red[w * 8 + h] = zl[h];
    }
    __syncthreads();
    if (tid < 8) {
        float z = 0.f;
#pragma unroll
        for (int ww = 0; ww < 16; ww++) z += red[ww * 8 + tid];
        invZ[tid] = 1.f / z;
    }
    __syncthreads();

    // ---- weighted_avg ----
    {
        const int hd = tid & 63, q8 = tid >> 6;
        const int h = hd >> 3, d = hd & 7;
        float pa = 0.f;
        const int sb = q8 * 128;
        for (int s = sb; s < sb + 128; ++s)
            pa += lsm[s * 8 + h] * vs[s * 8 + d];
        part[tid] = pa;
    }
    __syncthreads();
    if (tid < 64) {
        const int h = tid >> 3;
        float acc = 0.f;
#pragma unroll
        for (int k = 0; k < 8; k++) acc += part[tid + 64 * k];
        g_wa[r * 64 + tid] = acc * invZ[h];
    }
}

// ---------------------------------------------------------------------------
// Kernel 2: gate + output via tf32 MMA, coalesced global I/O.
// grid = (768, 8 s-tiles of 128 rows), 256 threads, warp owns 16-row strip.
// ---------------------------------------------------------------------------
__global__ void __launch_bounds__(256, 2) msa_k2(
    const float* __restrict__ act,
    const float* __restrict__ ln_scale, const float* __restrict__ ln_bias,
    const float* __restrict__ gating_w,  // [64, 64]
    const float* __restrict__ gating_b,  // [64]
    const float* __restrict__ output_w,  // [64, 64]
    const float* __restrict__ output_b,  // [64]
    float* __restrict__ out)             // [S, R, C]
{
    extern __shared__ float sm2[];
    float* xn_s = sm2;             // 128*68 = 8704
    float* gwt  = xn_s + 8704;     // 4352   gwt[j][c]
    float* owt  = gwt + 4352;      // 4352   owt[o][j]
    float* was  = owt + 4352;      // 64
    float* gbs  = was + 64;        // 64
    float* obs  = gbs + 64;        // 64
    float* scl  = obs + 64;        // 64
    float* bia  = scl + 64;        // 64

    const int tid  = threadIdx.x;
    const int r    = blockIdx.x;
    const int s0   = blockIdx.y * 128;
    const int w    = tid >> 5, lane = tid & 31;
    const int c4   = lane & 15, rsel = lane >> 4;

    for (int i = tid; i < 4096; i += 256) {
        gwt[(i & 63) * XS + (i >> 6)] = __uint_as_float(f2tf32(gating_w[i]));
        owt[(i & 63) * XS + (i >> 6)] = __uint_as_float(f2tf32(output_w[i]));
    }
    if (tid < 64) {
        was[tid] = g_wa[r * 64 + tid];
        gbs[tid] = gating_b[tid];  obs[tid] = output_b[tid];
        scl[tid] = ln_scale[tid];  bia[tid] = ln_bias[tid];
    }
    __syncthreads();

    // ---- LN: coalesced, 2 rows per warp-round, width-16 shfl reduce ----
    {
        const float4 sc = ((const float4*)scl)[c4];
        const float4 bi = ((const float4*)bia)[c4];
#pragma unroll
        for (int rnd = 0; rnd < 8; rnd++) {
            const int row = w * 16 + rnd * 2 + rsel;
            const float4 t = *(const float4*)(act + ((size_t)(s0 + row) * NRES + r) * CM + c4 * 4);
            float sum = t.x + t.y + t.z + t.w;
            sum += __shfl_xor_sync(0xffffffffu, sum, 1);
            sum += __shfl_xor_sync(0xffffffffu, sum, 2);
            sum += __shfl_xor_sync(0xffffffffu, sum, 4);
            sum += __shfl_xor_sync(0xffffffffu, sum, 8);
            const float mu = sum * (1.f / 64.f);
            float vv = (t.x-mu)*(t.x-mu) + (t.y-mu)*(t.y-mu)
                     + (t.z-mu)*(t.z-mu) + (t.w-mu)*(t.w-mu);
            vv += __shfl_xor_sync(0xffffffffu, vv, 1);
            vv += __shfl_xor_sync(0xffffffffu, vv, 2);
            vv += __shfl_xor_sync(0xffffffffu, vv, 4);
            vv += __shfl_xor_sync(0xffffffffu, vv, 8);
            const float rstd = rsqrtf(vv * (1.f / 64.f) + 1e-5f);
            float4 o;
            o.x = __uint_as_float(f2tf32((t.x - mu) * rstd * sc.x + bi.x));
            o.y = __uint_as_float(f2tf32((t.y - mu) * rstd * sc.y + bi.y));
            o.z = __uint_as_float(f2tf32((t.z - mu) * rstd * sc.z + bi.z));
            o.w = __uint_as_float(f2tf32((t.w - mu) * rstd * sc.w + bi.w));
            *(float4*)(xn_s + row * XS + c4 * 4) = o;
        }
    }
    __syncthreads();

    // ---- per-warp MMA pipeline on its 16-row strip ----
    const int g = lane >> 2, t = lane & 3;
    const int rb = w * 16;

    float4 acc[8];
#pragma unroll
    for (int n = 0; n < 8; n++) acc[n] = make_float4(0.f, 0.f, 0.f, 0.f);

#pragma unroll
    for (int k = 0; k < 8; k++) {
        const int kc = k * 8 + t;
        const uint32_t a0 = __float_as_uint(xn_s[(rb + g) * XS + kc]);
        const uint32_t a1 = __float_as_uint(xn_s[(rb + g + 8) * XS + kc]);
        const uint32_t a2 = __float_as_uint(xn_s[(rb + g) * XS + kc + 4]);
        const uint32_t a3 = __float_as_uint(xn_s[(rb + g + 8) * XS + kc + 4]);
#pragma unroll
        for (int n = 0; n < 8; n++) {
            const uint32_t b0 = __float_as_uint(gwt[(n * 8 + g) * XS + kc]);
            const uint32_t b1 = __float_as_uint(gwt[(n * 8 + g) * XS + kc + 4]);
            mma_tf32(acc[n], a0, a1, a2, a3, b0, b1);
        }
    }
    __syncwarp();

    // gate: G = wa * sigmoid(logits + gb), tf32, back into own strip
#pragma unroll
    for (int n = 0; n < 8; n++) {
        const int c0 = n * 8 + 2 * t, c1 = c0 + 1;
        const float w0 = was[c0], w1 = was[c1];
        const float b0 = gbs[c0], b1 = gbs[c1];
        xn_s[(rb + g) * XS + c0]     = __uint_as_float(f2tf32(w0 * sigf(acc[n].x + b0)));
        xn_s[(rb + g) * XS + c1]     = __uint_as_float(f2tf32(w1 * sigf(acc[n].y + b1)));
        xn_s[(rb + g + 8) * XS + c0] = __uint_as_float(f2tf32(w0 * sigf(acc[n].z + b0)));
        xn_s[(rb + g + 8) * XS + c1] = __uint_as_float(f2tf32(w1 * sigf(acc[n].w + b1)));
    }
    __syncwarp();

    // GEMM2: OUT = G @ OW + ob
    float4 o[8];
#pragma unroll
    for (int n = 0; n < 8; n++) {
        const int c0 = n * 8 + 2 * t;
        o[n] = make_float4(obs[c0], obs[c0 + 1], obs[c0], obs[c0 + 1]);
    }
#pragma unroll
    for (int k = 0; k < 8; k++) {
        const int kc = k * 8 + t;
        const uint32_t a0 = __float_as_uint(xn_s[(rb + g) * XS + kc]);
        const uint32_t a1 = __float_as_uint(xn_s[(rb + g + 8) * XS + kc]);
        const uint32_t a2 = __float_as_uint(xn_s[(rb + g) * XS + kc + 4]);
        const uint32_t a3 = __float_as_uint(xn_s[(rb + g + 8) * XS + kc + 4]);
#pragma unroll
        for (int n = 0; n < 8; n++) {
            const uint32_t b0 = __float_as_uint(owt[(n * 8 + g) * XS + kc]);
            const uint32_t b1 = __float_as_uint(owt[(n * 8 + g) * XS + kc + 4]);
            mma_tf32(o[n], a0, a1, a2, a3, b0, b1);
        }
    }
    __syncwarp();

    // stage results into own strip of xn_s (G no longer needed)
#pragma unroll
    for (int n = 0; n < 8; n++) {
        const int c0 = n * 8 + 2 * t;
        *(float2*)(xn_s + (rb + g) * XS + c0)     = make_float2(o[n].x, o[n].y);
        *(float2*)(xn_s + (rb + g + 8) * XS + c0) = make_float2(o[n].z, o[n].w);
    }
    __syncwarp();

    // coalesced STG: 2 rows per round
#pragma unroll
    for (int rnd = 0; rnd < 8; rnd++) {
        const int row = w * 16 + rnd * 2 + rsel;
        const float4 v = *(const float4*)(xn_s + row * XS + c4 * 4);
        *(float4*)(out + ((size_t)(s0 + row) * NRES + r) * CM + c4 * 4) = v;
    }
}

// ---------------------------------------------------------------------------
#define K1_SMEM (44945 * 4)
#define K2_SMEM (17888 * 4)

extern "C" void kernel_launch(void* const* d_in, const int* in_sizes, int n_in,
                              void* d_out, int out_size) {
    (void)in_sizes; (void)n_in; (void)out_size;
    const float* act      = (const float*)d_in[0];
    const float* mask     = (const float*)d_in[1];
    const float* ln_scale = (const float*)d_in[2];
    const float* ln_bias  = (const float*)d_in[3];
    const float* query_w  = (const float*)d_in[4];
    const float* key_w    = (const float*)d_in[5];
    const float* value_w  = (const float*)d_in[6];
    const float* gating_w = (const float*)d_in[7];
    const float* gating_b = (const float*)d_in[8];
    const float* output_w = (const float*)d_in[9];
    const float* output_b = (const float*)d_in[10];
    float* out = (float*)d_out;

    cudaFuncSetAttribute(msa_k1, cudaFuncAttributeMaxDynamicSharedMemorySize, K1_SMEM);
    cudaFuncSetAttribute(msa_k2, cudaFuncAttributeMaxDynamicSharedMemorySize, K2_SMEM);

    msa_k1<<<NRES, 512, K1_SMEM>>>(act, mask, ln_scale, ln_bias, query_w, key_w, value_w);
    msa_k2<<<dim3(NRES, 8), 256, K2_SMEM>>>(act, ln_scale, ln_bias,
                                            gating_w, gating_b, output_w, output_b, out);
}